// round 11
// baseline (speedup 1.0000x reference)
#include <cuda_runtime.h>
#include <cstdint>

// SpectralConv1d via pruned cas-FFT, persistent streaming transforms.
// forward: persistent blocks, cp.async double-buffered row prefetch,
//          4 reg levels -> in-place smem exchange -> 3 reg levels ->
//          specializing multi-shfl omega reduction
// mix:     cp.async double-buffered weights, 512 blocks, float4 g_Z stores
// inverse: persistent blocks, cp.async z prefetch, broadcast init,
//          reg levels, swizzled exchange, direct coalesced STG out

#define NN     4096
#define MODES  64
#define CH     128
#define ROWS   8192

#define SQ2   1.41421356237309515f
#define C256  1.30656296487637653f   // cas(pi/8)
#define C1280 0.54119610014619698f   // cas(5pi/8)

__device__ float g_CAS[2048];             // cas(2*pi*j/4096)
__device__ float g_OM[2048];              // omega[k<64][q<32]
__device__ float g_Y[MODES * ROWS];       // [m][row]
__device__ float g_Z[MODES * ROWS];       // [m][row]  (already /4096)
__device__ float g_We[MODES * CH * CH];   // [m][i][o]
__device__ float g_Wo[MODES * CH * CH];   // [m][i][o]

__device__ __forceinline__ void cp16(uint32_t daddr, const void* gptr) {
    asm volatile("cp.async.cg.shared.global [%0], [%1], 16;" :: "r"(daddr), "l"(gptr));
}
__device__ __forceinline__ void cp4(uint32_t daddr, const void* gptr) {
    asm volatile("cp.async.ca.shared.global [%0], [%1], 4;" :: "r"(daddr), "l"(gptr));
}
__device__ __forceinline__ void cp_commit() {
    asm volatile("cp.async.commit_group;" ::: "memory");
}
__device__ __forceinline__ void cp_wait1() {
    asm volatile("cp.async.wait_group 1;" ::: "memory");
}
__device__ __forceinline__ void cp_wait0() {
    asm volatile("cp.async.wait_group 0;" ::: "memory");
}

__global__ void build_tables_kernel() {
    int j = blockIdx.x * blockDim.x + threadIdx.x;
    if (j < 2048) {
        float s, c;
        sincospif((float)j * (1.0f / 2048.0f), &s, &c);
        g_CAS[j] = c + s;
    } else if (j < 4096) {
        int idx = j - 2048;
        int k = idx >> 5, q = idx & 31;
        float w = 1.0f;
        #pragma unroll
        for (int t = 0; t < 5; t++) {
            if ((q >> t) & 1) {
                float s, c;
                sincospif((float)(k << t) * (1.0f / 2048.0f), &s, &c);
                w *= (c + s);
            }
        }
        g_OM[idx] = w;
    }
}

// One block per i. Coalesced gmem read (m-fast), smem transpose (pad 129),
// coalesced gmem write (o-fast).
__global__ __launch_bounds__(256) void build_wewo_kernel(const float* __restrict__ w1) {
    __shared__ float tile[64 * 129];
    int i = blockIdx.x, tid = threadIdx.x;
    const float* src = w1 + (size_t)i * 8192;   // [o][m], m fast
    for (int idx = tid; idx < 8192; idx += 256) {
        int o = idx >> 6, m = idx & 63;
        tile[m * 129 + o] = src[idx];
    }
    __syncthreads();
    for (int j = tid; j < 8192; j += 256) {
        int m = j >> 7, o = j & 127;
        int mn = (MODES - m) & 63;
        float a = tile[m * 129 + o];
        float b = tile[mn * 129 + o];
        size_t d = (size_t)m * 16384 + (size_t)i * 128 + o;
        g_We[d] = 0.5f * (a + b);
        g_Wo[d] = 0.5f * (a - b);
    }
}

__device__ __forceinline__ int brev4(int r) {
    return ((r & 1) << 3) | ((r & 2) << 1) | ((r & 4) >> 1) | ((r & 8) >> 3);
}

// ---------------- forward (persistent, double-buffered) ----------------
#define FWD_GRID (148 * 6)

__global__ __launch_bounds__(256) void forward_kernel(const float* __restrict__ x) {
    __shared__ float rbuf[2][4096];    // row data; also reused as exchange buf
    __shared__ float cas32s[64];
    int h = threadIdx.x;
    int lane = h & 31, wrp = h >> 5;

    if (h < 64) cas32s[h] = g_CAS[h << 5];
    float om[8];
    #pragma unroll
    for (int c = 0; c < 8; c++) om[c] = g_OM[((wrp + (c << 3)) << 5) + lane];

    uint32_t rb_base = (uint32_t)__cvta_generic_to_shared(rbuf);
    const int step = gridDim.x;
    int row = blockIdx.x;

    if (row < ROWS) {
        const float4* src = (const float4*)(x + (size_t)row * NN);
        #pragma unroll
        for (int j = 0; j < 4; j++)
            cp16(rb_base + (uint32_t)(h + j * 256) * 16, src + h + j * 256);
    }
    cp_commit();

    int cur = 0;
    for (; row < ROWS; row += step) {
        int nrow = row + step;
        if (nrow < ROWS) {
            const float4* src = (const float4*)(x + (size_t)nrow * NN);
            uint32_t d = rb_base + (uint32_t)(cur ^ 1) * 16384;
            #pragma unroll
            for (int j = 0; j < 4; j++)
                cp16(d + (uint32_t)(h + j * 256) * 16, src + h + j * 256);
            cp_commit();
            cp_wait1();
        } else {
            cp_wait0();
        }
        __syncthreads();            // row data visible

        float* rb = rbuf[cur];
        float v[16];
        #pragma unroll
        for (int r = 0; r < 16; r++) v[r] = rb[h + (r << 8)];

        // stage 1: levels t=11,10 (tw=1), t=9, t=8 — const twiddles
        #pragma unroll
        for (int r = 0; r < 8; r++) { float a = v[r], b = v[r + 8]; v[r] = a + b; v[r + 8] = a - b; }
        #pragma unroll
        for (int r = 0; r < 16; r++) if (!(r & 4)) { float a = v[r], b = v[r + 4]; v[r] = a + b; v[r + 4] = a - b; }
        {
            const float TW9[4] = {1.f, SQ2, 1.f, 0.f};
            #pragma unroll
            for (int r = 0; r < 16; r++) if (!(r & 2)) {
                int kt = ((r >> 3) & 1) | (((r >> 2) & 1) << 1);
                float w = TW9[kt], a = v[r], b = v[r + 2];
                v[r] = fmaf(w, b, a); v[r + 2] = fmaf(-w, b, a);
            }
        }
        {
            const float TW8[8] = {1.f, C256, SQ2, C256, 1.f, C1280, 0.f, -C1280};
            #pragma unroll
            for (int r = 0; r < 16; r += 2) {
                int kt = ((r >> 3) & 1) | (((r >> 2) & 1) << 1) | (((r >> 1) & 1) << 2);
                float w = TW8[kt], a = v[r], b = v[r + 1];
                v[r] = fmaf(w, b, a); v[r + 1] = fmaf(-w, b, a);
            }
        }
        __syncthreads();            // all rb reads done (exchange aliases rb)
        #pragma unroll
        for (int r = 0; r < 16; r++) rb[h + (brev4(r) << 8)] = v[r];
        __syncthreads();

        // stage 2: free bits {5,6,7,11}
        int hi3 = wrp;
        int base = (h & 31) + (hi3 << 8);
        float u[16];
        #pragma unroll
        for (int r = 0; r < 16; r++) u[r] = rb[base + ((r & 7) << 5) + ((r & 8) << 8)];
        // t=7
        #pragma unroll
        for (int r = 0; r < 16; r++) if (!(r & 4)) {
            float w = cas32s[(hi3 + (r & 8)) << 2];
            float a = u[r], b = u[r + 4];
            u[r] = fmaf(w, b, a); u[r + 4] = fmaf(-w, b, a);
        }
        // t=6
        #pragma unroll
        for (int r = 0; r < 16; r++) if (!(r & 2)) {
            float w = cas32s[(hi3 + (r & 8) + ((r & 4) << 2)) << 1];
            float a = u[r], b = u[r + 2];
            u[r] = fmaf(w, b, a); u[r + 2] = fmaf(-w, b, a);
        }
        // t=5: only even outputs survive the k<64 prune
        #pragma unroll
        for (int r = 0; r < 16; r += 2) {
            float w = cas32s[hi3 + (r & 8) + ((r & 4) << 2) + ((r & 2) << 4)];
            u[r] = fmaf(w, u[r + 1], u[r]);
        }

        // tail: specializing multi-shfl reduction
        float val[8];
        #pragma unroll
        for (int c = 0; c < 8; c++) {
            int j = ((c & 1) << 2) | (c & 2) | ((c & 4) >> 2);  // brev3(c)
            val[c] = om[c] * u[2 * j];
        }
        bool b4 = (lane & 16) != 0, b3 = (lane & 8) != 0, b2 = (lane & 4) != 0;
        float a4[4];
        #pragma unroll
        for (int c = 0; c < 4; c++) {
            float keep = b4 ? val[c + 4] : val[c];
            float give = b4 ? val[c] : val[c + 4];
            a4[c] = keep + __shfl_xor_sync(0xffffffffu, give, 16);
        }
        float a2[2];
        #pragma unroll
        for (int c = 0; c < 2; c++) {
            float keep = b3 ? a4[c + 2] : a4[c];
            float give = b3 ? a4[c] : a4[c + 2];
            a2[c] = keep + __shfl_xor_sync(0xffffffffu, give, 8);
        }
        float e;
        {
            float keep = b2 ? a2[1] : a2[0];
            float give = b2 ? a2[0] : a2[1];
            e = keep + __shfl_xor_sync(0xffffffffu, give, 4);
        }
        e += __shfl_xor_sync(0xffffffffu, e, 2);
        e += __shfl_xor_sync(0xffffffffu, e, 1);
        if ((lane & 3) == 0) g_Y[(wrp + ((lane >> 2) << 3)) * ROWS + row] = e;

        __syncthreads();            // rb reads done before next prefetch/reuse
        cur ^= 1;
    }
}

// ---------------- mix (unchanged) ----------------
// grid = 512 (64 modes x 8 groups of 8 batches), 128 threads.
__global__ __launch_bounds__(128) void mix_kernel() {
    __shared__ float Ys[8 * CH];
    __shared__ float Yn[8 * CH];
    extern __shared__ float4 Wbuf[];   // [2 stages][2 mats][512 float4] = 32KB

    int m = blockIdx.x >> 3, g = blockIdx.x & 7;
    int mn = (MODES - m) & 63;
    int tid = threadIdx.x;
    int oq = tid & 31, bg = tid >> 5;

    const float* We = g_We + (size_t)m * 16384;
    const float* Wo = g_Wo + (size_t)m * 16384;
    uint32_t wb = (uint32_t)__cvta_generic_to_shared(Wbuf);

    #define ISSUE_CHUNK(c, s) do {                                              \
        const float4* se = (const float4*)(We + (c) * 2048);                    \
        const float4* so = (const float4*)(Wo + (c) * 2048);                    \
        uint32_t de = wb + (uint32_t)((s) * 2 + 0) * 8192;                      \
        uint32_t dn = wb + (uint32_t)((s) * 2 + 1) * 8192;                      \
        _Pragma("unroll")                                                       \
        for (int jj = 0; jj < 4; jj++) {                                        \
            int idx = tid + jj * 128;                                           \
            cp16(de + idx * 16, se + idx);                                      \
            cp16(dn + idx * 16, so + idx);                                      \
        }                                                                       \
        cp_commit();                                                            \
    } while (0)

    ISSUE_CHUNK(0, 0);
    ISSUE_CHUNK(1, 1);

    for (int idx = tid; idx < 1024; idx += 128) {
        Ys[idx] = g_Y[m * ROWS + g * 1024 + idx];
        Yn[idx] = g_Y[mn * ROWS + g * 1024 + idx];
    }

    float4 a0 = {0,0,0,0}, a1 = {0,0,0,0};
    int l0 = 2 * bg, l1 = l0 + 1;

    #pragma unroll 1
    for (int c = 0; c < 8; c++) {
        if (c < 7) cp_wait1(); else cp_wait0();
        __syncthreads();

        const float4* Wef = &Wbuf[(size_t)((c & 1) * 2 + 0) * 512];
        const float4* Wof = &Wbuf[(size_t)((c & 1) * 2 + 1) * 512];
        #pragma unroll
        for (int ii = 0; ii < 16; ii++) {
            float4 we = Wef[ii * 32 + oq];
            float4 wo = Wof[ii * 32 + oq];
            int i = c * 16 + ii;
            float y0 = Ys[l0 * CH + i], z0 = Yn[l0 * CH + i];
            float y1 = Ys[l1 * CH + i], z1 = Yn[l1 * CH + i];
            a0.x = fmaf(y0, we.x, a0.x); a0.x = fmaf(z0, wo.x, a0.x);
            a0.y = fmaf(y0, we.y, a0.y); a0.y = fmaf(z0, wo.y, a0.y);
            a0.z = fmaf(y0, we.z, a0.z); a0.z = fmaf(z0, wo.z, a0.z);
            a0.w = fmaf(y0, we.w, a0.w); a0.w = fmaf(z0, wo.w, a0.w);
            a1.x = fmaf(y1, we.x, a1.x); a1.x = fmaf(z1, wo.x, a1.x);
            a1.y = fmaf(y1, we.y, a1.y); a1.y = fmaf(z1, wo.y, a1.y);
            a1.z = fmaf(y1, we.z, a1.z); a1.z = fmaf(z1, wo.z, a1.z);
            a1.w = fmaf(y1, we.w, a1.w); a1.w = fmaf(z1, wo.w, a1.w);
        }
        __syncthreads();
        if (c < 6) ISSUE_CHUNK(c + 2, c & 1);
    }

    const float inv = 1.0f / 4096.0f;
    float4* Z4 = (float4*)g_Z;
    float4 s0 = make_float4(a0.x * inv, a0.y * inv, a0.z * inv, a0.w * inv);
    float4 s1 = make_float4(a1.x * inv, a1.y * inv, a1.z * inv, a1.w * inv);
    int b0 = g * 8 + l0;
    Z4[(size_t)m * 2048 + (size_t)b0 * 32 + oq]       = s0;
    Z4[(size_t)m * 2048 + (size_t)(b0 + 1) * 32 + oq] = s1;
    #undef ISSUE_CHUNK
}

// ---------------- inverse (persistent, z prefetch) ----------------
#define INV_GRID (148 * 8)

__global__ __launch_bounds__(256) void inverse_kernel(float* __restrict__ out) {
    __shared__ float buf[4096];
    __shared__ float cas_s[2048];
    __shared__ float zb[2][64];
    int h = threadIdx.x;

    for (int j = h; j < 2048; j += 256) cas_s[j] = g_CAS[j];   // once per block
    uint32_t zba = (uint32_t)__cvta_generic_to_shared(zb);
    const int step = gridDim.x;
    int row = blockIdx.x;

    if (row < ROWS && h < 64) cp4(zba + (uint32_t)h * 4, &g_Z[(size_t)h * ROWS + row]);
    cp_commit();

    int cur = 0;
    for (; row < ROWS; row += step) {
        int nrow = row + step;
        if (nrow < ROWS) {
            if (h < 64)
                cp4(zba + (uint32_t)(cur ^ 1) * 256 + (uint32_t)h * 4,
                    &g_Z[(size_t)h * ROWS + nrow]);
            cp_commit();
            cp_wait1();
        } else {
            cp_wait0();
        }
        __syncthreads();           // zb[cur] visible; buf free from prev iter

        const float* z = zb[cur];
        float v[16];
        #pragma unroll
        for (int r = 0; r < 16; r++) v[r] = z[(h & 7) + ((r & 7) << 3)];

        int hk = (h >> 3) & 31;
        #pragma unroll
        for (int r = 0; r < 16; r++) if (!(r & 4)) {
            float w = cas_s[(hk + ((r & 8) << 2)) << 5];
            float a = v[r], b = v[r + 4];
            v[r] = fmaf(w, b, a); v[r + 4] = fmaf(-w, b, a);
        }
        #pragma unroll
        for (int r = 0; r < 16; r++) if (!(r & 2)) {
            float w = cas_s[(hk + ((r & 8) << 2) + ((r & 4) << 4)) << 4];
            float a = v[r], b = v[r + 2];
            v[r] = fmaf(w, b, a); v[r + 2] = fmaf(-w, b, a);
        }
        #pragma unroll
        for (int r = 0; r < 16; r += 2) {
            float w = cas_s[(hk + ((r & 8) << 2) + ((r & 4) << 4) + ((r & 2) << 6)) << 3];
            float a = v[r], b = v[r + 1];
            v[r] = fmaf(w, b, a); v[r + 1] = fmaf(-w, b, a);
        }

        #pragma unroll
        for (int r = 0; r < 16; r++) {
            int a = h + (brev4(r) << 8);
            buf[a ^ ((a >> 5) & 7)] = v[r];
        }
        __syncthreads();
        #pragma unroll
        for (int r = 0; r < 16; r++) {
            int a = (r & 7) + (h << 3) + ((r & 8) << 8);
            v[r] = buf[a ^ ((a >> 5) & 7)];
        }

        #pragma unroll
        for (int r = 0; r < 16; r++) if (!(r & 4)) {
            float w = cas_s[(h + ((r & 8) << 5)) << 2];
            float a = v[r], b = v[r + 4];
            v[r] = fmaf(w, b, a); v[r + 4] = fmaf(-w, b, a);
        }
        #pragma unroll
        for (int r = 0; r < 16; r++) if (!(r & 2)) {
            float w = cas_s[(h + ((r & 8) << 5) + ((r & 4) << 7)) << 1];
            float a = v[r], b = v[r + 2];
            v[r] = fmaf(w, b, a); v[r + 2] = fmaf(-w, b, a);
        }
        #pragma unroll
        for (int r = 0; r < 16; r += 2) {
            float w = cas_s[h + ((r & 8) << 5) + ((r & 4) << 7) + ((r & 2) << 9)];
            float a = v[r], b = v[r + 1];
            v[r] = fmaf(w, b, a); v[r + 1] = fmaf(-w, b, a);
        }

        float* orow = out + (size_t)row * NN;
        #pragma unroll
        for (int r = 0; r < 16; r++) orow[h + (brev4(r) << 8)] = v[r];

        __syncthreads();           // buf reads done before next iter's writes
        cur ^= 1;
    }
}

extern "C" void kernel_launch(void* const* d_in, const int* in_sizes, int n_in,
                              void* d_out, int out_size) {
    const float* x  = (const float*)d_in[0];
    const float* w1 = (const float*)d_in[1];
    float* out = (float*)d_out;

    build_tables_kernel<<<16, 256>>>();
    build_wewo_kernel<<<CH, 256>>>(w1);
    forward_kernel<<<FWD_GRID, 256>>>(x);
    mix_kernel<<<MODES * 8, 128, 32768>>>();
    inverse_kernel<<<INV_GRID, 256>>>(out);
}

// round 12
// speedup vs baseline: 1.3935x; 1.3935x over previous
#include <cuda_runtime.h>
#include <cstdint>

// SpectralConv1d via pruned cas-FFT (R9 structure, measured best 105.2us).
// forward: 4 reg levels -> smem exchange -> 3 reg levels (even-only t=5)
//          -> omega dot-products via specializing multi-shfl reduction
// mix:     cp.async double-buffered weights, 512 blocks, float4 g_Z stores
// inverse: broadcast init, reg levels, swizzled exchange, direct STG.32 out
// R11 delta: __launch_bounds__(256, 6) on forward/inverse to raise residency.

#define NN     4096
#define MODES  64
#define CH     128
#define ROWS   8192

#define SQ2   1.41421356237309515f
#define C256  1.30656296487637653f   // cas(pi/8)
#define C1280 0.54119610014619698f   // cas(5pi/8)

__device__ float g_CAS[2048];             // cas(2*pi*j/4096)
__device__ float g_OM[2048];              // omega[k<64][q<32]
__device__ float g_Y[MODES * ROWS];       // [m][row]
__device__ float g_Z[MODES * ROWS];       // [m][row]  (already /4096)
__device__ float g_We[MODES * CH * CH];   // [m][i][o]
__device__ float g_Wo[MODES * CH * CH];   // [m][i][o]

__global__ void build_tables_kernel() {
    int j = blockIdx.x * blockDim.x + threadIdx.x;
    if (j < 2048) {
        float s, c;
        sincospif((float)j * (1.0f / 2048.0f), &s, &c);
        g_CAS[j] = c + s;
    } else if (j < 4096) {
        int idx = j - 2048;
        int k = idx >> 5, q = idx & 31;
        float w = 1.0f;
        #pragma unroll
        for (int t = 0; t < 5; t++) {
            if ((q >> t) & 1) {
                float s, c;
                sincospif((float)(k << t) * (1.0f / 2048.0f), &s, &c);
                w *= (c + s);
            }
        }
        g_OM[idx] = w;
    }
}

// One block per i. Coalesced gmem read (m-fast), smem transpose (pad 129),
// coalesced gmem write (o-fast).
__global__ __launch_bounds__(256) void build_wewo_kernel(const float* __restrict__ w1) {
    __shared__ float tile[64 * 129];
    int i = blockIdx.x, tid = threadIdx.x;
    const float* src = w1 + (size_t)i * 8192;   // [o][m], m fast
    for (int idx = tid; idx < 8192; idx += 256) {
        int o = idx >> 6, m = idx & 63;
        tile[m * 129 + o] = src[idx];
    }
    __syncthreads();
    for (int j = tid; j < 8192; j += 256) {
        int m = j >> 7, o = j & 127;
        int mn = (MODES - m) & 63;
        float a = tile[m * 129 + o];
        float b = tile[mn * 129 + o];
        size_t d = (size_t)m * 16384 + (size_t)i * 128 + o;
        g_We[d] = 0.5f * (a + b);
        g_Wo[d] = 0.5f * (a - b);
    }
}

__device__ __forceinline__ int brev4(int r) {
    return ((r & 1) << 3) | ((r & 2) << 1) | ((r & 4) >> 1) | ((r & 8) >> 3);
}

// ---------------- forward ----------------
__global__ __launch_bounds__(256, 6) void forward_kernel(const float* __restrict__ x) {
    __shared__ float buf[4096];
    __shared__ float cas32s[64];
    int h = threadIdx.x, row = blockIdx.x;
    int lane = h & 31, wrp = h >> 5;

    if (h < 64) cas32s[h] = g_CAS[h << 5];

    const float* xr = x + (size_t)row * NN;
    float v[16];
    #pragma unroll
    for (int r = 0; r < 16; r++) v[r] = xr[h + (r << 8)];

    // omega rows: om[c] is the (k = wrp + 8c, q = lane) entry — coalesced
    float om[8];
    #pragma unroll
    for (int c = 0; c < 8; c++) om[c] = g_OM[((wrp + (c << 3)) << 5) + lane];

    // stage 1: levels t=11,10 (tw=1), t=9, t=8 — const twiddles
    #pragma unroll
    for (int r = 0; r < 8; r++) { float a = v[r], b = v[r + 8]; v[r] = a + b; v[r + 8] = a - b; }
    #pragma unroll
    for (int r = 0; r < 16; r++) if (!(r & 4)) { float a = v[r], b = v[r + 4]; v[r] = a + b; v[r + 4] = a - b; }
    {
        const float TW9[4] = {1.f, SQ2, 1.f, 0.f};
        #pragma unroll
        for (int r = 0; r < 16; r++) if (!(r & 2)) {
            int kt = ((r >> 3) & 1) | (((r >> 2) & 1) << 1);
            float w = TW9[kt], a = v[r], b = v[r + 2];
            v[r] = fmaf(w, b, a); v[r + 2] = fmaf(-w, b, a);
        }
    }
    {
        const float TW8[8] = {1.f, C256, SQ2, C256, 1.f, C1280, 0.f, -C1280};
        #pragma unroll
        for (int r = 0; r < 16; r += 2) {
            int kt = ((r >> 3) & 1) | (((r >> 2) & 1) << 1) | (((r >> 1) & 1) << 2);
            float w = TW8[kt], a = v[r], b = v[r + 1];
            v[r] = fmaf(w, b, a); v[r + 1] = fmaf(-w, b, a);
        }
    }
    // exchange (depth-8 layout)
    #pragma unroll
    for (int r = 0; r < 16; r++) buf[h + (brev4(r) << 8)] = v[r];
    __syncthreads();

    // stage 2: free bits {5,6,7,11}
    int hi3 = wrp;
    int base = (h & 31) + (hi3 << 8);
    float u[16];
    #pragma unroll
    for (int r = 0; r < 16; r++) u[r] = buf[base + ((r & 7) << 5) + ((r & 8) << 8)];
    // t=7
    #pragma unroll
    for (int r = 0; r < 16; r++) if (!(r & 4)) {
        float w = cas32s[(hi3 + (r & 8)) << 2];
        float a = u[r], b = u[r + 4];
        u[r] = fmaf(w, b, a); u[r + 4] = fmaf(-w, b, a);
    }
    // t=6
    #pragma unroll
    for (int r = 0; r < 16; r++) if (!(r & 2)) {
        float w = cas32s[(hi3 + (r & 8) + ((r & 4) << 2)) << 1];
        float a = u[r], b = u[r + 2];
        u[r] = fmaf(w, b, a); u[r + 2] = fmaf(-w, b, a);
    }
    // t=5: only even outputs survive the k<64 prune
    #pragma unroll
    for (int r = 0; r < 16; r += 2) {
        float w = cas32s[hi3 + (r & 8) + ((r & 4) << 2) + ((r & 2) << 4)];
        u[r] = fmaf(w, u[r + 1], u[r]);
    }

    // tail: Y[k = wrp + 8c] = sum_q om[c][q] * D5-chunk value.
    // Specializing multi-reduction: halve accumulator count each stage.
    float val[8];
    #pragma unroll
    for (int c = 0; c < 8; c++) {
        int j = ((c & 1) << 2) | (c & 2) | ((c & 4) >> 2);  // brev3(c)
        val[c] = om[c] * u[2 * j];
    }
    bool b4 = (lane & 16) != 0, b3 = (lane & 8) != 0, b2 = (lane & 4) != 0;
    float a4[4];
    #pragma unroll
    for (int c = 0; c < 4; c++) {
        float keep = b4 ? val[c + 4] : val[c];
        float give = b4 ? val[c] : val[c + 4];
        a4[c] = keep + __shfl_xor_sync(0xffffffffu, give, 16);
    }
    float a2[2];
    #pragma unroll
    for (int c = 0; c < 2; c++) {
        float keep = b3 ? a4[c + 2] : a4[c];
        float give = b3 ? a4[c] : a4[c + 2];
        a2[c] = keep + __shfl_xor_sync(0xffffffffu, give, 8);
    }
    float e;
    {
        float keep = b2 ? a2[1] : a2[0];
        float give = b2 ? a2[0] : a2[1];
        e = keep + __shfl_xor_sync(0xffffffffu, give, 4);
    }
    e += __shfl_xor_sync(0xffffffffu, e, 2);
    e += __shfl_xor_sync(0xffffffffu, e, 1);
    // lane L holds Y[wrp + 8*((L>>2)&7)]; one writer per group of 4
    if ((lane & 3) == 0) g_Y[(wrp + ((lane >> 2) << 3)) * ROWS + row] = e;
}

// ---------------- mix ----------------
// grid = 512 (64 modes x 8 groups of 8 batches), 128 threads.
// thread (oq = tid&31, bg = tid>>5): 2 batches x 4 outputs, 8 accums.
__device__ __forceinline__ void cp16(uint32_t daddr, const void* gptr) {
    asm volatile("cp.async.cg.shared.global [%0], [%1], 16;" :: "r"(daddr), "l"(gptr));
}

__global__ __launch_bounds__(128) void mix_kernel() {
    __shared__ float Ys[8 * CH];
    __shared__ float Yn[8 * CH];
    extern __shared__ float4 Wbuf[];   // [2 stages][2 mats][512 float4] = 32KB

    int m = blockIdx.x >> 3, g = blockIdx.x & 7;
    int mn = (MODES - m) & 63;
    int tid = threadIdx.x;
    int oq = tid & 31, bg = tid >> 5;

    const float* We = g_We + (size_t)m * 16384;
    const float* Wo = g_Wo + (size_t)m * 16384;
    uint32_t wb = (uint32_t)__cvta_generic_to_shared(Wbuf);

    #define ISSUE_CHUNK(c, s) do {                                              \
        const float4* se = (const float4*)(We + (c) * 2048);                    \
        const float4* so = (const float4*)(Wo + (c) * 2048);                    \
        uint32_t de = wb + (uint32_t)((s) * 2 + 0) * 8192;                      \
        uint32_t dn = wb + (uint32_t)((s) * 2 + 1) * 8192;                      \
        _Pragma("unroll")                                                       \
        for (int jj = 0; jj < 4; jj++) {                                        \
            int idx = tid + jj * 128;                                           \
            cp16(de + idx * 16, se + idx);                                      \
            cp16(dn + idx * 16, so + idx);                                      \
        }                                                                       \
        asm volatile("cp.async.commit_group;" ::: "memory");                    \
    } while (0)

    ISSUE_CHUNK(0, 0);
    ISSUE_CHUNK(1, 1);

    for (int idx = tid; idx < 1024; idx += 128) {
        Ys[idx] = g_Y[m * ROWS + g * 1024 + idx];
        Yn[idx] = g_Y[mn * ROWS + g * 1024 + idx];
    }

    float4 a0 = {0,0,0,0}, a1 = {0,0,0,0};
    int l0 = 2 * bg, l1 = l0 + 1;

    #pragma unroll 1
    for (int c = 0; c < 8; c++) {
        if (c < 7) asm volatile("cp.async.wait_group 1;" ::: "memory");
        else       asm volatile("cp.async.wait_group 0;" ::: "memory");
        __syncthreads();

        const float4* Wef = &Wbuf[(size_t)((c & 1) * 2 + 0) * 512];
        const float4* Wof = &Wbuf[(size_t)((c & 1) * 2 + 1) * 512];
        #pragma unroll
        for (int ii = 0; ii < 16; ii++) {
            float4 we = Wef[ii * 32 + oq];
            float4 wo = Wof[ii * 32 + oq];
            int i = c * 16 + ii;
            float y0 = Ys[l0 * CH + i], z0 = Yn[l0 * CH + i];
            float y1 = Ys[l1 * CH + i], z1 = Yn[l1 * CH + i];
            a0.x = fmaf(y0, we.x, a0.x); a0.x = fmaf(z0, wo.x, a0.x);
            a0.y = fmaf(y0, we.y, a0.y); a0.y = fmaf(z0, wo.y, a0.y);
            a0.z = fmaf(y0, we.z, a0.z); a0.z = fmaf(z0, wo.z, a0.z);
            a0.w = fmaf(y0, we.w, a0.w); a0.w = fmaf(z0, wo.w, a0.w);
            a1.x = fmaf(y1, we.x, a1.x); a1.x = fmaf(z1, wo.x, a1.x);
            a1.y = fmaf(y1, we.y, a1.y); a1.y = fmaf(z1, wo.y, a1.y);
            a1.z = fmaf(y1, we.z, a1.z); a1.z = fmaf(z1, wo.z, a1.z);
            a1.w = fmaf(y1, we.w, a1.w); a1.w = fmaf(z1, wo.w, a1.w);
        }
        __syncthreads();
        if (c < 6) ISSUE_CHUNK(c + 2, c & 1);
    }

    // g_Z layout [m][row]: thread's 4 consecutive-o accums -> one STG.128.
    const float inv = 1.0f / 4096.0f;
    float4* Z4 = (float4*)g_Z;
    float4 s0 = make_float4(a0.x * inv, a0.y * inv, a0.z * inv, a0.w * inv);
    float4 s1 = make_float4(a1.x * inv, a1.y * inv, a1.z * inv, a1.w * inv);
    int b0 = g * 8 + l0;
    Z4[(size_t)m * 2048 + (size_t)b0 * 32 + oq]       = s0;
    Z4[(size_t)m * 2048 + (size_t)(b0 + 1) * 32 + oq] = s1;
    #undef ISSUE_CHUNK
}

// ---------------- inverse ----------------
__global__ __launch_bounds__(256, 6) void inverse_kernel(float* __restrict__ out) {
    __shared__ float buf[4096];
    __shared__ float cas_s[2048];
    __shared__ float zb[64];
    int h = threadIdx.x, row = blockIdx.x;

    for (int j = h; j < 2048; j += 256) cas_s[j] = g_CAS[j];
    if (h < 64) zb[h] = g_Z[(size_t)h * ROWS + row];   // [m][row] layout
    __syncthreads();

    float v[16];
    #pragma unroll
    for (int r = 0; r < 16; r++) v[r] = zb[(h & 7) + ((r & 7) << 3)];

    int hk = (h >> 3) & 31;
    #pragma unroll
    for (int r = 0; r < 16; r++) if (!(r & 4)) {
        float w = cas_s[(hk + ((r & 8) << 2)) << 5];
        float a = v[r], b = v[r + 4];
        v[r] = fmaf(w, b, a); v[r + 4] = fmaf(-w, b, a);
    }
    #pragma unroll
    for (int r = 0; r < 16; r++) if (!(r & 2)) {
        float w = cas_s[(hk + ((r & 8) << 2) + ((r & 4) << 4)) << 4];
        float a = v[r], b = v[r + 2];
        v[r] = fmaf(w, b, a); v[r + 2] = fmaf(-w, b, a);
    }
    #pragma unroll
    for (int r = 0; r < 16; r += 2) {
        float w = cas_s[(hk + ((r & 8) << 2) + ((r & 4) << 4) + ((r & 2) << 6)) << 3];
        float a = v[r], b = v[r + 1];
        v[r] = fmaf(w, b, a); v[r + 1] = fmaf(-w, b, a);
    }

    #pragma unroll
    for (int r = 0; r < 16; r++) {
        int a = h + (brev4(r) << 8);
        buf[a ^ ((a >> 5) & 7)] = v[r];
    }
    __syncthreads();
    #pragma unroll
    for (int r = 0; r < 16; r++) {
        int a = (r & 7) + (h << 3) + ((r & 8) << 8);
        v[r] = buf[a ^ ((a >> 5) & 7)];
    }

    #pragma unroll
    for (int r = 0; r < 16; r++) if (!(r & 4)) {
        float w = cas_s[(h + ((r & 8) << 5)) << 2];
        float a = v[r], b = v[r + 4];
        v[r] = fmaf(w, b, a); v[r + 4] = fmaf(-w, b, a);
    }
    #pragma unroll
    for (int r = 0; r < 16; r++) if (!(r & 2)) {
        float w = cas_s[(h + ((r & 8) << 5) + ((r & 4) << 7)) << 1];
        float a = v[r], b = v[r + 2];
        v[r] = fmaf(w, b, a); v[r + 2] = fmaf(-w, b, a);
    }
    #pragma unroll
    for (int r = 0; r < 16; r += 2) {
        float w = cas_s[h + ((r & 8) << 5) + ((r & 4) << 7) + ((r & 2) << 9)];
        float a = v[r], b = v[r + 1];
        v[r] = fmaf(w, b, a); v[r + 1] = fmaf(-w, b, a);
    }

    // direct coalesced stores: lane addresses consecutive per instruction
    float* orow = out + (size_t)row * NN;
    #pragma unroll
    for (int r = 0; r < 16; r++) orow[h + (brev4(r) << 8)] = v[r];
}

extern "C" void kernel_launch(void* const* d_in, const int* in_sizes, int n_in,
                              void* d_out, int out_size) {
    const float* x  = (const float*)d_in[0];
    const float* w1 = (const float*)d_in[1];
    float* out = (float*)d_out;

    build_tables_kernel<<<16, 256>>>();
    build_wewo_kernel<<<CH, 256>>>(w1);
    forward_kernel<<<ROWS, 256>>>(x);
    mix_kernel<<<MODES * 8, 128, 32768>>>();
    inverse_kernel<<<ROWS, 256>>>(out);
}